// round 15
// baseline (speedup 1.0000x reference)
#include <cuda_runtime.h>
#include <cuda_fp16.h>
#include <math.h>
#include <stdint.h>

// Problem constants
#define N_Q   65536
#define N_E   1024
#define DIM   64
#define HW    4096
#define TOTAL 4194304    // 16*64*4096
#define MQ    64         // queries per CTA

// Output layout: loss[1] | quantized[TOTAL] | perplexity[1] | encodings[N_Q*N_E]
#define O_QUANT 1UL
#define O_PERP  4194305UL
#define O_ENC   4194306UL

// ---------------- device scratch --------------------------------------------------
__device__ __align__(256) __half g_eh[N_E * DIM];
__device__ __align__(256) __half g_el[N_E * DIM];
__device__ int      g_counts[N_E];
__device__ float    g_loss_accum;
__device__ float    g_enorm_half[N_E];
__device__ unsigned g_done;

// ---------------- mma / ldmatrix helpers (base PTX ISA, no 'a' feature) -----------
__device__ __forceinline__ uint32_t smem_u32(const void* p) {
    uint32_t a;
    asm("{ .reg .u64 t; cvta.to.shared.u64 t, %1; cvt.u32.u64 %0, t; }" : "=r"(a) : "l"(p));
    return a;
}
__device__ __forceinline__ void ldsm_x4(uint32_t* r, uint32_t addr) {
    asm volatile("ldmatrix.sync.aligned.m8n8.x4.shared.b16 {%0,%1,%2,%3}, [%4];"
                 : "=r"(r[0]), "=r"(r[1]), "=r"(r[2]), "=r"(r[3]) : "r"(addr));
}
__device__ __forceinline__ void mma16816(float* c, const uint32_t* a, const uint32_t* b) {
    asm volatile("mma.sync.aligned.m16n8k16.row.col.f32.f16.f16.f32 "
                 "{%0,%1,%2,%3}, {%4,%5,%6,%7}, {%8,%9}, {%0,%1,%2,%3};"
                 : "+f"(c[0]), "+f"(c[1]), "+f"(c[2]), "+f"(c[3])
                 : "r"(a[0]), "r"(a[1]), "r"(a[2]), "r"(a[3]), "r"(b[0]), "r"(b[1]));
}

// ---------------- prep: codebook split + norms + zero accum (1 warp / code) --------
__global__ void prep_e_kernel(const float* __restrict__ ew) {
    int wid  = threadIdx.x >> 5;           // 8 warps per block
    int lane = threadIdx.x & 31;
    int j = blockIdx.x * 8 + wid;          // code index, grid 128
    float2 v = *(const float2*)&ew[(size_t)j * DIM + lane * 2];
    __half h0 = __float2half_rn(v.x);
    __half l0 = __float2half_rn(v.x - __half2float(h0));
    __half h1 = __float2half_rn(v.y);
    __half l1 = __float2half_rn(v.y - __half2float(h1));
    *(__half2*)&g_eh[(size_t)j * DIM + lane * 2] = __halves2half2(h0, h1);
    *(__half2*)&g_el[(size_t)j * DIM + lane * 2] = __halves2half2(l0, l1);
    float s = v.x * v.x + v.y * v.y;
#pragma unroll
    for (int m = 16; m > 0; m >>= 1) s += __shfl_xor_sync(0xffffffffu, s, m);
    if (lane == 0) {
        g_enorm_half[j] = 0.5f * s;
        g_counts[j] = 0;
        if (j == 0) { g_loss_accum = 0.0f; g_done = 0u; }
    }
}

// ---------------- kernel A: fully fused VQ, M=64/CTA, 4 CTAs/SM ---------------------
// smem layout (bytes). X tiles [64 rows][LDH=72 halves], E tiles [128][72]
#define LDH 72
#define LDQ 65
#define SM_XH 0                        //  9216
#define SM_XL 9216                     //  9216
#define SM_EH 18432                    // 18432
#define SM_EL 36864                    // 18432
#define SM_EN 55296                    // 128 floats
#define SM_RV 55808                    // red_val: 64*4 floats
#define SM_RI 56832                    // red_idx: 64*4 ints
#define SM_IX 57856                    // final idx: 64 ints
#define SM_SZ 58112
// 4 x 58112 = 232448 <= 228KB. quant tile qt[64][LDQ] reuses EH in the tail.

__global__ __launch_bounds__(256, 4) void argmin_mma_kernel(const float* __restrict__ x,
                                                            const float* __restrict__ ew,
                                                            float* __restrict__ out) {
    extern __shared__ char smem[];
    __shared__ unsigned s_last;
    uint32_t sb = smem_u32(smem);
    int tid  = threadIdx.x;
    int wid  = tid >> 5, lane = tid & 31;
    int wm   = wid & 1;        // m-block 0..1 (32 rows each)
    int wn   = wid >> 1;       // n-block 0..3 (32 cols each)
    int qbase = blockIdx.x * MQ;
    int b   = qbase >> 12;          // batch
    int hw0 = qbase & (HW - 1);     // hw offset (tile never crosses batch)

    float* ensm   = (float*)(smem + SM_EN);
    float* redv   = (float*)(smem + SM_RV);
    int*   redi   = (int*)  (smem + SM_RI);
    int*   sm_ix  = (int*)  (smem + SM_IX);
    __half* Xs  = (__half*)(smem + SM_XH);
    __half* XLs = (__half*)(smem + SM_XL);

    float* encbase = out + O_ENC + (size_t)qbase * N_E;

    // ---- fused prep_x: load 64 queries from NCHW, split to hi/lo fp16 in smem -----
    const float* xg = x + (size_t)b * (DIM * HW) + hw0;
#pragma unroll 4
    for (int i = 0; i < 16; i++) {
        int linear = i * 256 + tid;
        int k = linear >> 6, h = linear & 63;
        float v = xg[(size_t)k * HW + h];         // coalesced
        __half hi = __float2half_rn(v);
        __half lo = __float2half_rn(v - __half2float(hi));
        Xs [h * LDH + k] = hi;
        XLs[h * LDH + k] = lo;
    }

    int aRow = wm * 32 + (lane & 15);
    int aKof = (lane >> 4) * 8;
    // B x4 addressing: lanes 0-7 slab nib k-half0, 8-15 slab nib k-half1,
    // 16-23 slab nib+1 half0, 24-31 slab nib+1 half1.
    int bNi  = (lane >> 4) & 1;
    int bKof = ((lane >> 3) & 1) * 8;
    int bRow = wn * 32 + (lane & 7);

    float bestV[4];
    int   bestI[4];
#pragma unroll
    for (int s = 0; s < 4; s++) { bestV[s] = 3.4e38f; bestI[s] = 0; }

    for (int chunk = 0; chunk < 8; chunk++) {
        int j0 = chunk * 128;
        __syncthreads();
        if (tid < 128) ensm[tid] = g_enorm_half[j0 + tid];
        for (int i = tid; i < 1024; i += 256) {
            int r = i >> 3, s = i & 7;
            uint32_t off = (uint32_t)(r * LDH + s * 8) * 2;
            *(uint4*)(smem + SM_EH + off) = *(const uint4*)&g_eh[(size_t)(j0 + r) * DIM + s * 8];
            *(uint4*)(smem + SM_EL + off) = *(const uint4*)&g_el[(size_t)(j0 + r) * DIM + s * 8];
        }
        __syncthreads();

        float acc[2][4][4];
#pragma unroll
        for (int mi = 0; mi < 2; mi++)
#pragma unroll
            for (int ni = 0; ni < 4; ni++)
#pragma unroll
                for (int r = 0; r < 4; r++) acc[mi][ni][r] = 0.0f;

#pragma unroll
        for (int ks = 0; ks < 4; ks++) {
            int k0 = ks * 16;
            uint32_t ah[2][4], bh[4][2];
#pragma unroll
            for (int mi = 0; mi < 2; mi++)
                ldsm_x4(ah[mi], sb + SM_XH + (uint32_t)((aRow + mi * 16) * LDH + k0 + aKof) * 2);
#pragma unroll
            for (int nib = 0; nib < 4; nib += 2) {
                uint32_t r4[4];
                ldsm_x4(r4, sb + SM_EH +
                        (uint32_t)((bRow + (nib + bNi) * 8) * LDH + k0 + bKof) * 2);
                bh[nib][0] = r4[0]; bh[nib][1] = r4[1];
                bh[nib + 1][0] = r4[2]; bh[nib + 1][1] = r4[3];
            }
#pragma unroll
            for (int mi = 0; mi < 2; mi++)
#pragma unroll
                for (int ni = 0; ni < 4; ni++) mma16816(acc[mi][ni], ah[mi], bh[ni]);

            uint32_t bl[4][2];
#pragma unroll
            for (int nib = 0; nib < 4; nib += 2) {
                uint32_t r4[4];
                ldsm_x4(r4, sb + SM_EL +
                        (uint32_t)((bRow + (nib + bNi) * 8) * LDH + k0 + bKof) * 2);
                bl[nib][0] = r4[0]; bl[nib][1] = r4[1];
                bl[nib + 1][0] = r4[2]; bl[nib + 1][1] = r4[3];
            }
#pragma unroll
            for (int mi = 0; mi < 2; mi++)
#pragma unroll
                for (int ni = 0; ni < 4; ni++) mma16816(acc[mi][ni], ah[mi], bl[ni]);

            uint32_t al[2][4];
#pragma unroll
            for (int mi = 0; mi < 2; mi++)
                ldsm_x4(al[mi], sb + SM_XL + (uint32_t)((aRow + mi * 16) * LDH + k0 + aKof) * 2);
#pragma unroll
            for (int mi = 0; mi < 2; mi++)
#pragma unroll
                for (int ni = 0; ni < 4; ni++) mma16816(acc[mi][ni], al[mi], bh[ni]);
        }

        // ---- interleaved COALESCED enc zero-fill (after k-loop) --------------------
        // Chunks 0-3: 10 rows, 4-6: 8 rows, 7: none (64 rows total).
        {
            int nrows = (chunk < 4) ? 10 : ((chunk < 7) ? 8 : 0);
            int rbase = (chunk < 4) ? chunk * 10 : 40 + (chunk - 4) * 8;
            const float4 z4 = make_float4(0.0f, 0.0f, 0.0f, 0.0f);
            for (int r = 0; r < nrows; r++) {
                float* row = encbase + (size_t)(rbase + r) * N_E;
                if (tid < 255) {
                    __stcs((float4*)(row + 2 + 4 * tid), z4);
                } else {
                    __stcs((float2*)row, make_float2(0.0f, 0.0f));
                    __stcs((float2*)(row + 1022), make_float2(0.0f, 0.0f));
                }
            }
        }

        // epilogue: per-row argmin over this chunk's 128 codes
        float enr[8];
#pragma unroll
        for (int ni = 0; ni < 4; ni++) {
            int j = wn * 32 + ni * 8 + (lane & 3) * 2;
            enr[ni * 2]     = ensm[j];
            enr[ni * 2 + 1] = ensm[j + 1];
        }
        int g = lane >> 2;
#pragma unroll
        for (int mi = 0; mi < 2; mi++) {
#pragma unroll
            for (int h = 0; h < 2; h++) {
                float v = 3.4e38f; int ix = 0;
#pragma unroll
                for (int ni = 0; ni < 4; ni++) {
#pragma unroll
                    for (int bb = 0; bb < 2; bb++) {
                        float cand = enr[ni * 2 + bb] - acc[mi][ni][h * 2 + bb];
                        int col = j0 + wn * 32 + ni * 8 + (lane & 3) * 2 + bb;
                        if (cand < v) { v = cand; ix = col; }
                    }
                }
#pragma unroll
                for (int m = 1; m < 4; m <<= 1) {
                    float ov = __shfl_xor_sync(0xffffffffu, v, m);
                    int   oi = __shfl_xor_sync(0xffffffffu, ix, m);
                    if (ov < v || (ov == v && oi < ix)) { v = ov; ix = oi; }
                }
                if ((lane & 3) == 0) {
                    int row = wm * 32 + mi * 16 + g + h * 8;
                    redv[row * 4 + wn] = v;
                    redi[row * 4 + wn] = ix;
                }
            }
        }
        __syncthreads();

        if (wn == 0 && (lane & 3) == 0) {
            int slot = 0;
#pragma unroll
            for (int mi = 0; mi < 2; mi++) {
#pragma unroll
                for (int h = 0; h < 2; h++) {
                    int row = wm * 32 + mi * 16 + g + h * 8;
#pragma unroll
                    for (int w = 0; w < 4; w++) {
                        float ov = redv[row * 4 + w];
                        int   oi = redi[row * 4 + w];
                        if (ov < bestV[slot] || (ov == bestV[slot] && oi < bestI[slot])) {
                            bestV[slot] = ov; bestI[slot] = oi;
                        }
                    }
                    slot++;
                }
            }
        }
    }

    if (wn == 0 && (lane & 3) == 0) {
        int g = lane >> 2;
        int slot = 0;
#pragma unroll
        for (int mi = 0; mi < 2; mi++) {
#pragma unroll
            for (int h = 0; h < 2; h++) {
                int row = wm * 32 + mi * 16 + g + h * 8;
                sm_ix[row] = bestI[slot];
                atomicAdd(&g_counts[bestI[slot]], 1);
                slot++;
            }
        }
    }
    __syncthreads();   // orders all zero stores + sm_ix before hot stores

    // ---- hot one-hot stores: 64 scalar writes ---------------------------------------
    if (tid < MQ) {
        int idx = sm_ix[tid];
        __stcs(encbase + (size_t)tid * N_E + idx, 1.0f);
    }

    // ---- fused quantize + straight-through + loss -----------------------------------
    // Phase 1: gather ew rows into qt[k][h] in the dead EH region; XH/XL survive.
    float* qt = (float*)(smem + SM_EH);   // [64][LDQ] = 16640 B
    {
        int h = tid & 63, quarter = tid >> 6;   // 4 threads per row, 16 dims each
        int idx = sm_ix[h];
        const float4* er = (const float4*)(ew + (size_t)idx * DIM + quarter * 16);
#pragma unroll
        for (int i = 0; i < 4; i++) {
            float4 v = er[i];
            int k = quarter * 16 + i * 4;
            qt[(k + 0) * LDQ + h] = v.x;
            qt[(k + 1) * LDQ + h] = v.y;
            qt[(k + 2) * LDQ + h] = v.z;
            qt[(k + 3) * LDQ + h] = v.w;
        }
    }
    __syncthreads();

    // Phase 2: x reconstructed from smem (hi+lo); no DRAM x re-read.
    float* qout = out + O_QUANT + (size_t)b * (DIM * HW) + hw0;
    float lsum = 0.0f;
#pragma unroll 4
    for (int i = 0; i < 16; i++) {
        int linear = i * 256 + tid;
        int k = linear >> 6, h = linear & 63;
        float xv = __half2float(Xs[h * LDH + k]) + __half2float(XLs[h * LDH + k]);
        float q  = qt[k * LDQ + h];
        float d  = q - xv;
        qout[(size_t)k * HW + h] = xv + d;   // straight-through forward value
        lsum += d * d;
    }
#pragma unroll
    for (int m = 16; m > 0; m >>= 1) lsum += __shfl_xor_sync(0xffffffffu, lsum, m);
    if (lane == 0) redv[wid] = lsum;
    __syncthreads();
    if (tid == 0) {
        float v = 0.0f;
#pragma unroll
        for (int w = 0; w < 8; w++) v += redv[w];
        atomicAdd(&g_loss_accum, v);
        __threadfence();
        unsigned prev = atomicAdd(&g_done, 1u);
        s_last = (prev == (unsigned)(gridDim.x - 1)) ? 1u : 0u;
    }
    __syncthreads();

    // ---- last CTA finalizes loss + perplexity ----------------------------------------
    if (s_last) {
        float s = 0.0f;
#pragma unroll
        for (int i = 0; i < 4; i++) {
            float p = (float)g_counts[tid * 4 + i] * (1.0f / 65536.0f);
            s += p * logf(p + 1e-10f);
        }
#pragma unroll
        for (int m = 16; m > 0; m >>= 1) s += __shfl_xor_sync(0xffffffffu, s, m);
        if (lane == 0) redv[wid] = s;
        __syncthreads();
        if (tid == 0) {
            float v = 0.0f;
#pragma unroll
            for (int w = 0; w < 8; w++) v += redv[w];
            out[O_PERP] = expf(-v);
            out[0] = 1.25f * g_loss_accum * (1.0f / (float)TOTAL);
        }
    }
}

// ---------------- launch ---------------------------------------------------------------
extern "C" void kernel_launch(void* const* d_in, const int* in_sizes, int n_in,
                              void* d_out, int out_size) {
    const float* x  = (const float*)d_in[0];
    const float* ew = (const float*)d_in[1];
    if (n_in >= 2 && in_sizes[0] == N_E * DIM && in_sizes[1] == TOTAL) {
        x  = (const float*)d_in[1];
        ew = (const float*)d_in[0];
    }
    float* out = (float*)d_out;

    prep_e_kernel<<<N_E / 8, 256>>>(ew);

    cudaFuncSetAttribute(argmin_mma_kernel,
                         cudaFuncAttributeMaxDynamicSharedMemorySize, SM_SZ);
    argmin_mma_kernel<<<N_Q / MQ, 256, SM_SZ>>>(x, ew, out);
}

// round 16
// speedup vs baseline: 1.1240x; 1.1240x over previous
#include <cuda_runtime.h>
#include <cuda_fp16.h>
#include <math.h>
#include <stdint.h>

// Problem constants
#define N_Q   65536
#define N_E   1024
#define DIM   64
#define HW    4096
#define TOTAL 4194304    // 16*64*4096
#define MQ    64         // queries per CTA

// Output layout: loss[1] | quantized[TOTAL] | perplexity[1] | encodings[N_Q*N_E]
#define O_QUANT 1UL
#define O_PERP  4194305UL
#define O_ENC   4194306UL

// ---------------- device scratch --------------------------------------------------
__device__ __align__(256) __half g_eh[N_E * DIM];
__device__ __align__(256) __half g_el[N_E * DIM];
__device__ int      g_counts[N_E];
__device__ float    g_loss_accum;
__device__ float    g_enorm_half[N_E];
__device__ unsigned g_done;

// ---------------- mma / ldmatrix helpers (base PTX ISA, no 'a' feature) -----------
__device__ __forceinline__ uint32_t smem_u32(const void* p) {
    uint32_t a;
    asm("{ .reg .u64 t; cvta.to.shared.u64 t, %1; cvt.u32.u64 %0, t; }" : "=r"(a) : "l"(p));
    return a;
}
__device__ __forceinline__ void ldsm_x4(uint32_t* r, uint32_t addr) {
    asm volatile("ldmatrix.sync.aligned.m8n8.x4.shared.b16 {%0,%1,%2,%3}, [%4];"
                 : "=r"(r[0]), "=r"(r[1]), "=r"(r[2]), "=r"(r[3]) : "r"(addr));
}
__device__ __forceinline__ void mma16816(float* c, const uint32_t* a, const uint32_t* b) {
    asm volatile("mma.sync.aligned.m16n8k16.row.col.f32.f16.f16.f32 "
                 "{%0,%1,%2,%3}, {%4,%5,%6,%7}, {%8,%9}, {%0,%1,%2,%3};"
                 : "+f"(c[0]), "+f"(c[1]), "+f"(c[2]), "+f"(c[3])
                 : "r"(a[0]), "r"(a[1]), "r"(a[2]), "r"(a[3]), "r"(b[0]), "r"(b[1]));
}

// SW128 swizzle for 128-byte rows (XOR bits [7:9] into bits [4:6])
#define SW(x) ((uint32_t)(x) ^ ((((uint32_t)(x)) >> 3) & 0x70u))

// ---------------- prep: codebook split + norms + zero accum (1 warp / code) --------
__global__ void prep_e_kernel(const float* __restrict__ ew) {
    int wid  = threadIdx.x >> 5;           // 8 warps per block
    int lane = threadIdx.x & 31;
    int j = blockIdx.x * 8 + wid;          // code index, grid 128
    float2 v = *(const float2*)&ew[(size_t)j * DIM + lane * 2];
    __half h0 = __float2half_rn(v.x);
    __half l0 = __float2half_rn(v.x - __half2float(h0));
    __half h1 = __float2half_rn(v.y);
    __half l1 = __float2half_rn(v.y - __half2float(h1));
    *(__half2*)&g_eh[(size_t)j * DIM + lane * 2] = __halves2half2(h0, h1);
    *(__half2*)&g_el[(size_t)j * DIM + lane * 2] = __halves2half2(l0, l1);
    float s = v.x * v.x + v.y * v.y;
#pragma unroll
    for (int m = 16; m > 0; m >>= 1) s += __shfl_xor_sync(0xffffffffu, s, m);
    if (lane == 0) {
        g_enorm_half[j] = 0.5f * s;
        g_counts[j] = 0;
        if (j == 0) { g_loss_accum = 0.0f; g_done = 0u; }
    }
}

// ---------------- kernel A: fully fused VQ, M=64/CTA, 4 CTAs/SM ---------------------
// smem layout (bytes). X tiles padded [64][LDH=72]; E tiles SWIZZLED [128][64].
#define LDH 72
#define LDQ 65
#define SM_XH 0                        //  9216
#define SM_XL 9216                     //  9216
#define SM_EH 18432                    // 16384 (swizzled, 128B rows)
#define SM_EL 34816                    // 16384
#define SM_EN 51200                    // 128 floats
#define SM_RV 51712                    // red_val: 64*4 floats
#define SM_RI 52736                    // red_idx: 64*4 ints
#define SM_IX 53760                    // final idx: 64 ints
#define SM_SZ 54016
// 54016 -> 7 x 8KB pages -> 4 CTAs/SM (4*57344 = 229376 <= 228KB carveout).
// quant tile qt[64][LDQ] (16640B) reuses EH+EL in the tail; XH/XL survive.

__global__ __launch_bounds__(256, 4) void argmin_mma_kernel(const float* __restrict__ x,
                                                            const float* __restrict__ ew,
                                                            float* __restrict__ out) {
    extern __shared__ char smem[];
    __shared__ unsigned s_last;
    uint32_t sb = smem_u32(smem);
    int tid  = threadIdx.x;
    int wid  = tid >> 5, lane = tid & 31;
    int wm   = wid & 1;        // m-block 0..1 (32 rows each)
    int wn   = wid >> 1;       // n-block 0..3 (32 cols each)
    int qbase = blockIdx.x * MQ;
    int b   = qbase >> 12;          // batch
    int hw0 = qbase & (HW - 1);     // hw offset (tile never crosses batch)

    float* ensm   = (float*)(smem + SM_EN);
    float* redv   = (float*)(smem + SM_RV);
    int*   redi   = (int*)  (smem + SM_RI);
    int*   sm_ix  = (int*)  (smem + SM_IX);
    __half* Xs  = (__half*)(smem + SM_XH);
    __half* XLs = (__half*)(smem + SM_XL);

    float* encbase = out + O_ENC + (size_t)qbase * N_E;

    // ---- fused prep_x: load 64 queries from NCHW, split to hi/lo fp16 in smem -----
    const float* xg = x + (size_t)b * (DIM * HW) + hw0;
#pragma unroll 4
    for (int i = 0; i < 16; i++) {
        int linear = i * 256 + tid;
        int k = linear >> 6, h = linear & 63;
        float v = xg[(size_t)k * HW + h];         // coalesced
        __half hi = __float2half_rn(v);
        __half lo = __float2half_rn(v - __half2float(hi));
        Xs [h * LDH + k] = hi;
        XLs[h * LDH + k] = lo;
    }

    int aRow = wm * 32 + (lane & 15);
    int aKof = (lane >> 4) * 8;
    // B x4 addressing (swizzled E tiles, 128B rows)
    int bNi  = (lane >> 4) & 1;
    int bKof = ((lane >> 3) & 1) * 8;
    int bRow = wn * 32 + (lane & 7);

    float bestV[4];
    int   bestI[4];
#pragma unroll
    for (int s = 0; s < 4; s++) { bestV[s] = 3.4e38f; bestI[s] = 0; }

    for (int chunk = 0; chunk < 8; chunk++) {
        int j0 = chunk * 128;
        __syncthreads();
        if (tid < 128) ensm[tid] = g_enorm_half[j0 + tid];
        for (int i = tid; i < 1024; i += 256) {
            int r = i >> 3, s = i & 7;
            uint32_t off = SW((uint32_t)(r * 128 + s * 16));
            *(uint4*)(smem + SM_EH + off) = *(const uint4*)&g_eh[(size_t)(j0 + r) * DIM + s * 8];
            *(uint4*)(smem + SM_EL + off) = *(const uint4*)&g_el[(size_t)(j0 + r) * DIM + s * 8];
        }
        __syncthreads();

        float acc[2][4][4];
#pragma unroll
        for (int mi = 0; mi < 2; mi++)
#pragma unroll
            for (int ni = 0; ni < 4; ni++)
#pragma unroll
                for (int r = 0; r < 4; r++) acc[mi][ni][r] = 0.0f;

#pragma unroll
        for (int ks = 0; ks < 4; ks++) {
            int k0 = ks * 16;
            uint32_t ah[2][4], bh[4][2];
#pragma unroll
            for (int mi = 0; mi < 2; mi++)
                ldsm_x4(ah[mi], sb + SM_XH + (uint32_t)((aRow + mi * 16) * LDH + k0 + aKof) * 2);
#pragma unroll
            for (int nib = 0; nib < 4; nib += 2) {
                uint32_t r4[4];
                uint32_t off = SW((uint32_t)((bRow + (nib + bNi) * 8) * 128 + (k0 + bKof) * 2));
                ldsm_x4(r4, sb + SM_EH + off);
                bh[nib][0] = r4[0]; bh[nib][1] = r4[1];
                bh[nib + 1][0] = r4[2]; bh[nib + 1][1] = r4[3];
            }
#pragma unroll
            for (int mi = 0; mi < 2; mi++)
#pragma unroll
                for (int ni = 0; ni < 4; ni++) mma16816(acc[mi][ni], ah[mi], bh[ni]);

            uint32_t bl[4][2];
#pragma unroll
            for (int nib = 0; nib < 4; nib += 2) {
                uint32_t r4[4];
                uint32_t off = SW((uint32_t)((bRow + (nib + bNi) * 8) * 128 + (k0 + bKof) * 2));
                ldsm_x4(r4, sb + SM_EL + off);
                bl[nib][0] = r4[0]; bl[nib][1] = r4[1];
                bl[nib + 1][0] = r4[2]; bl[nib + 1][1] = r4[3];
            }
#pragma unroll
            for (int mi = 0; mi < 2; mi++)
#pragma unroll
                for (int ni = 0; ni < 4; ni++) mma16816(acc[mi][ni], ah[mi], bl[ni]);

            uint32_t al[2][4];
#pragma unroll
            for (int mi = 0; mi < 2; mi++)
                ldsm_x4(al[mi], sb + SM_XL + (uint32_t)((aRow + mi * 16) * LDH + k0 + aKof) * 2);
#pragma unroll
            for (int mi = 0; mi < 2; mi++)
#pragma unroll
                for (int ni = 0; ni < 4; ni++) mma16816(acc[mi][ni], al[mi], bh[ni]);
        }

        // ---- interleaved COALESCED enc zero-fill (after k-loop) --------------------
        // Chunks 0-3: 10 rows, 4-6: 8 rows, 7: none (64 rows total).
        {
            int nrows = (chunk < 4) ? 10 : ((chunk < 7) ? 8 : 0);
            int rbase = (chunk < 4) ? chunk * 10 : 40 + (chunk - 4) * 8;
            const float4 z4 = make_float4(0.0f, 0.0f, 0.0f, 0.0f);
            for (int r = 0; r < nrows; r++) {
                float* row = encbase + (size_t)(rbase + r) * N_E;
                if (tid < 255) {
                    __stcs((float4*)(row + 2 + 4 * tid), z4);
                } else {
                    __stcs((float2*)row, make_float2(0.0f, 0.0f));
                    __stcs((float2*)(row + 1022), make_float2(0.0f, 0.0f));
                }
            }
        }

        // epilogue: per-row argmin over this chunk's 128 codes
        float enr[8];
#pragma unroll
        for (int ni = 0; ni < 4; ni++) {
            int j = wn * 32 + ni * 8 + (lane & 3) * 2;
            enr[ni * 2]     = ensm[j];
            enr[ni * 2 + 1] = ensm[j + 1];
        }
        int g = lane >> 2;
#pragma unroll
        for (int mi = 0; mi < 2; mi++) {
#pragma unroll
            for (int h = 0; h < 2; h++) {
                float v = 3.4e38f; int ix = 0;
#pragma unroll
                for (int ni = 0; ni < 4; ni++) {
#pragma unroll
                    for (int bb = 0; bb < 2; bb++) {
                        float cand = enr[ni * 2 + bb] - acc[mi][ni][h * 2 + bb];
                        int col = j0 + wn * 32 + ni * 8 + (lane & 3) * 2 + bb;
                        if (cand < v) { v = cand; ix = col; }
                    }
                }
#pragma unroll
                for (int m = 1; m < 4; m <<= 1) {
                    float ov = __shfl_xor_sync(0xffffffffu, v, m);
                    int   oi = __shfl_xor_sync(0xffffffffu, ix, m);
                    if (ov < v || (ov == v && oi < ix)) { v = ov; ix = oi; }
                }
                if ((lane & 3) == 0) {
                    int row = wm * 32 + mi * 16 + g + h * 8;
                    redv[row * 4 + wn] = v;
                    redi[row * 4 + wn] = ix;
                }
            }
        }
        __syncthreads();

        if (wn == 0 && (lane & 3) == 0) {
            int slot = 0;
#pragma unroll
            for (int mi = 0; mi < 2; mi++) {
#pragma unroll
                for (int h = 0; h < 2; h++) {
                    int row = wm * 32 + mi * 16 + g + h * 8;
#pragma unroll
                    for (int w = 0; w < 4; w++) {
                        float ov = redv[row * 4 + w];
                        int   oi = redi[row * 4 + w];
                        if (ov < bestV[slot] || (ov == bestV[slot] && oi < bestI[slot])) {
                            bestV[slot] = ov; bestI[slot] = oi;
                        }
                    }
                    slot++;
                }
            }
        }
    }

    if (wn == 0 && (lane & 3) == 0) {
        int g = lane >> 2;
        int slot = 0;
#pragma unroll
        for (int mi = 0; mi < 2; mi++) {
#pragma unroll
            for (int h = 0; h < 2; h++) {
                int row = wm * 32 + mi * 16 + g + h * 8;
                sm_ix[row] = bestI[slot];
                atomicAdd(&g_counts[bestI[slot]], 1);
                slot++;
            }
        }
    }
    __syncthreads();   // orders all zero stores + sm_ix before hot stores

    // ---- hot one-hot stores: 64 scalar writes ---------------------------------------
    if (tid < MQ) {
        int idx = sm_ix[tid];
        __stcs(encbase + (size_t)tid * N_E + idx, 1.0f);
    }

    // ---- fused quantize + straight-through + loss -----------------------------------
    // Phase 1: gather ew rows into qt[k][h] across the dead EH+EL region; XH/XL survive.
    float* qt = (float*)(smem + SM_EH);   // [64][LDQ] = 16640 B (fits in 32768)
    {
        int h = tid & 63, quarter = tid >> 6;   // 4 threads per row, 16 dims each
        int idx = sm_ix[h];
        const float4* er = (const float4*)(ew + (size_t)idx * DIM + quarter * 16);
#pragma unroll
        for (int i = 0; i < 4; i++) {
            float4 v = er[i];
            int k = quarter * 16 + i * 4;
            qt[(k + 0) * LDQ + h] = v.x;
            qt[(k + 1) * LDQ + h] = v.y;
            qt[(k + 2) * LDQ + h] = v.z;
            qt[(k + 3) * LDQ + h] = v.w;
        }
    }
    __syncthreads();

    // Phase 2: x reconstructed from smem (hi+lo); no DRAM x re-read.
    float* qout = out + O_QUANT + (size_t)b * (DIM * HW) + hw0;
    float lsum = 0.0f;
#pragma unroll 4
    for (int i = 0; i < 16; i++) {
        int linear = i * 256 + tid;
        int k = linear >> 6, h = linear & 63;
        float xv = __half2float(Xs[h * LDH + k]) + __half2float(XLs[h * LDH + k]);
        float q  = qt[k * LDQ + h];
        float d  = q - xv;
        qout[(size_t)k * HW + h] = xv + d;   // straight-through forward value
        lsum += d * d;
    }
#pragma unroll
    for (int m = 16; m > 0; m >>= 1) lsum += __shfl_xor_sync(0xffffffffu, lsum, m);
    if (lane == 0) redv[wid] = lsum;
    __syncthreads();
    if (tid == 0) {
        float v = 0.0f;
#pragma unroll
        for (int w = 0; w < 8; w++) v += redv[w];
        atomicAdd(&g_loss_accum, v);
        __threadfence();
        unsigned prev = atomicAdd(&g_done, 1u);
        s_last = (prev == (unsigned)(gridDim.x - 1)) ? 1u : 0u;
    }
    __syncthreads();

    // ---- last CTA finalizes loss + perplexity ----------------------------------------
    if (s_last) {
        float s = 0.0f;
#pragma unroll
        for (int i = 0; i < 4; i++) {
            float p = (float)g_counts[tid * 4 + i] * (1.0f / 65536.0f);
            s += p * logf(p + 1e-10f);
        }
#pragma unroll
        for (int m = 16; m > 0; m >>= 1) s += __shfl_xor_sync(0xffffffffu, s, m);
        if (lane == 0) redv[wid] = s;
        __syncthreads();
        if (tid == 0) {
            float v = 0.0f;
#pragma unroll
            for (int w = 0; w < 8; w++) v += redv[w];
            out[O_PERP] = expf(-v);
            out[0] = 1.25f * g_loss_accum * (1.0f / (float)TOTAL);
        }
    }
}

// ---------------- launch ---------------------------------------------------------------
extern "C" void kernel_launch(void* const* d_in, const int* in_sizes, int n_in,
                              void* d_out, int out_size) {
    const float* x  = (const float*)d_in[0];
    const float* ew = (const float*)d_in[1];
    if (n_in >= 2 && in_sizes[0] == N_E * DIM && in_sizes[1] == TOTAL) {
        x  = (const float*)d_in[1];
        ew = (const float*)d_in[0];
    }
    float* out = (float*)d_out;

    prep_e_kernel<<<N_E / 8, 256>>>(ew);

    cudaFuncSetAttribute(argmin_mma_kernel,
                         cudaFuncAttributeMaxDynamicSharedMemorySize, SM_SZ);
    argmin_mma_kernel<<<N_Q / MQ, 256, SM_SZ>>>(x, ew, out);
}

// round 17
// speedup vs baseline: 1.1647x; 1.0362x over previous
#include <cuda_runtime.h>
#include <cuda_fp16.h>
#include <math.h>
#include <stdint.h>

// Problem constants
#define N_Q   65536
#define N_E   1024
#define DIM   64
#define HW    4096
#define TOTAL 4194304    // 16*64*4096
#define MQ    64         // queries per CTA

// Output layout: loss[1] | quantized[TOTAL] | perplexity[1] | encodings[N_Q*N_E]
#define O_QUANT 1UL
#define O_PERP  4194305UL
#define O_ENC   4194306UL

// ---------------- device scratch --------------------------------------------------
__device__ __align__(256) __half g_eh[N_E * DIM];
__device__ __align__(256) __half g_el[N_E * DIM];
__device__ int      g_counts[N_E];
__device__ float    g_loss_accum;
__device__ float    g_enorm_half[N_E];
__device__ unsigned g_done;

// ---------------- mma / ldmatrix helpers (base PTX ISA, no 'a' feature) -----------
__device__ __forceinline__ uint32_t smem_u32(const void* p) {
    uint32_t a;
    asm("{ .reg .u64 t; cvta.to.shared.u64 t, %1; cvt.u32.u64 %0, t; }" : "=r"(a) : "l"(p));
    return a;
}
__device__ __forceinline__ void ldsm_x4(uint32_t* r, uint32_t addr) {
    asm volatile("ldmatrix.sync.aligned.m8n8.x4.shared.b16 {%0,%1,%2,%3}, [%4];"
                 : "=r"(r[0]), "=r"(r[1]), "=r"(r[2]), "=r"(r[3]) : "r"(addr));
}
__device__ __forceinline__ void mma16816(float* c, const uint32_t* a, const uint32_t* b) {
    asm volatile("mma.sync.aligned.m16n8k16.row.col.f32.f16.f16.f32 "
                 "{%0,%1,%2,%3}, {%4,%5,%6,%7}, {%8,%9}, {%0,%1,%2,%3};"
                 : "+f"(c[0]), "+f"(c[1]), "+f"(c[2]), "+f"(c[3])
                 : "r"(a[0]), "r"(a[1]), "r"(a[2]), "r"(a[3]), "r"(b[0]), "r"(b[1]));
}

// SW128 swizzle for 128-byte rows (XOR bits [7:9] into bits [4:6])
#define SW(x) ((uint32_t)(x) ^ ((((uint32_t)(x)) >> 3) & 0x70u))

// ---------------- prep: codebook split + norms + zero accum (1 warp / code) --------
__global__ void prep_e_kernel(const float* __restrict__ ew) {
    int wid  = threadIdx.x >> 5;           // 8 warps per block
    int lane = threadIdx.x & 31;
    int j = blockIdx.x * 8 + wid;          // code index, grid 128
    float2 v = *(const float2*)&ew[(size_t)j * DIM + lane * 2];
    __half h0 = __float2half_rn(v.x);
    __half l0 = __float2half_rn(v.x - __half2float(h0));
    __half h1 = __float2half_rn(v.y);
    __half l1 = __float2half_rn(v.y - __half2float(h1));
    *(__half2*)&g_eh[(size_t)j * DIM + lane * 2] = __halves2half2(h0, h1);
    *(__half2*)&g_el[(size_t)j * DIM + lane * 2] = __halves2half2(l0, l1);
    float s = v.x * v.x + v.y * v.y;
#pragma unroll
    for (int m = 16; m > 0; m >>= 1) s += __shfl_xor_sync(0xffffffffu, s, m);
    if (lane == 0) {
        g_enorm_half[j] = 0.5f * s;
        g_counts[j] = 0;
        if (j == 0) { g_loss_accum = 0.0f; g_done = 0u; }
    }
}

// ---------------- kernel A: fully fused VQ, M=64/CTA, 4 CTAs/SM ---------------------
// smem layout (bytes). X tiles padded [64][LDH=72]; E tiles SWIZZLED [128][64].
#define LDH 72
#define LDQ 65
#define SM_XH 0                        //  9216
#define SM_XL 9216                     //  9216
#define SM_EH 18432                    // 16384 (swizzled, 128B rows)
#define SM_EL 34816                    // 16384
#define SM_RV 51200                    // red_val: 64*4 floats = 1024
#define SM_RI 52224                    // red_idx: 64*4 ints  = 1024
#define SM_IX 53248                    // final idx: 64 ints
#define SM_SZ 53504
// 53504 -> 7 x 8KB pages -> 4 CTAs/SM. qt[64][LDQ] reuses EH+EL in the tail.

__global__ __launch_bounds__(256, 4) void argmin_mma_kernel(const float* __restrict__ x,
                                                            const float* __restrict__ ew,
                                                            float* __restrict__ out) {
    extern __shared__ char smem[];
    __shared__ unsigned s_last;
    uint32_t sb = smem_u32(smem);
    int tid  = threadIdx.x;
    int wid  = tid >> 5, lane = tid & 31;
    int wm   = wid & 1;        // m-block 0..1 (32 rows each)
    int wn   = wid >> 1;       // n-block 0..3 (32 cols each)
    int qbase = blockIdx.x * MQ;
    int b   = qbase >> 12;          // batch
    int hw0 = qbase & (HW - 1);     // hw offset (tile never crosses batch)

    float* redv   = (float*)(smem + SM_RV);
    int*   redi   = (int*)  (smem + SM_RI);
    int*   sm_ix  = (int*)  (smem + SM_IX);
    __half* Xs  = (__half*)(smem + SM_XH);
    __half* XLs = (__half*)(smem + SM_XL);

    float* encbase = out + O_ENC + (size_t)qbase * N_E;

    // ---- fused prep_x: load 64 queries from NCHW, split to hi/lo fp16 in smem -----
    const float* xg = x + (size_t)b * (DIM * HW) + hw0;
#pragma unroll 4
    for (int i = 0; i < 16; i++) {
        int linear = i * 256 + tid;
        int k = linear >> 6, h = linear & 63;
        float v = xg[(size_t)k * HW + h];         // coalesced
        __half hi = __float2half_rn(v);
        __half lo = __float2half_rn(v - __half2float(hi));
        Xs [h * LDH + k] = hi;
        XLs[h * LDH + k] = lo;
    }

    int aRow = wm * 32 + (lane & 15);
    int aKof = (lane >> 4) * 8;
    int bNi  = (lane >> 4) & 1;
    int bKof = ((lane >> 3) & 1) * 8;
    int bRow = wn * 32 + (lane & 7);

    // per-warp running best across all chunks (this warp's 32-col slab)
    float bestV[4];
    int   bestI[4];
#pragma unroll
    for (int s = 0; s < 4; s++) { bestV[s] = 3.4e38f; bestI[s] = 0; }

    for (int chunk = 0; chunk < 8; chunk++) {
        int j0 = chunk * 128;
        __syncthreads();   // prior-chunk E consumers done before overwrite
        for (int i = tid; i < 1024; i += 256) {
            int r = i >> 3, s = i & 7;
            uint32_t off = SW((uint32_t)(r * 128 + s * 16));
            *(uint4*)(smem + SM_EH + off) = *(const uint4*)&g_eh[(size_t)(j0 + r) * DIM + s * 8];
            *(uint4*)(smem + SM_EL + off) = *(const uint4*)&g_el[(size_t)(j0 + r) * DIM + s * 8];
        }
        __syncthreads();

        float acc[2][4][4];
#pragma unroll
        for (int mi = 0; mi < 2; mi++)
#pragma unroll
            for (int ni = 0; ni < 4; ni++)
#pragma unroll
                for (int r = 0; r < 4; r++) acc[mi][ni][r] = 0.0f;

#pragma unroll
        for (int ks = 0; ks < 4; ks++) {
            int k0 = ks * 16;
            uint32_t ah[2][4], bh[4][2];
#pragma unroll
            for (int mi = 0; mi < 2; mi++)
                ldsm_x4(ah[mi], sb + SM_XH + (uint32_t)((aRow + mi * 16) * LDH + k0 + aKof) * 2);
#pragma unroll
            for (int nib = 0; nib < 4; nib += 2) {
                uint32_t r4[4];
                uint32_t off = SW((uint32_t)((bRow + (nib + bNi) * 8) * 128 + (k0 + bKof) * 2));
                ldsm_x4(r4, sb + SM_EH + off);
                bh[nib][0] = r4[0]; bh[nib][1] = r4[1];
                bh[nib + 1][0] = r4[2]; bh[nib + 1][1] = r4[3];
            }
#pragma unroll
            for (int mi = 0; mi < 2; mi++)
#pragma unroll
                for (int ni = 0; ni < 4; ni++) mma16816(acc[mi][ni], ah[mi], bh[ni]);

            uint32_t bl[4][2];
#pragma unroll
            for (int nib = 0; nib < 4; nib += 2) {
                uint32_t r4[4];
                uint32_t off = SW((uint32_t)((bRow + (nib + bNi) * 8) * 128 + (k0 + bKof) * 2));
                ldsm_x4(r4, sb + SM_EL + off);
                bl[nib][0] = r4[0]; bl[nib][1] = r4[1];
                bl[nib + 1][0] = r4[2]; bl[nib + 1][1] = r4[3];
            }
#pragma unroll
            for (int mi = 0; mi < 2; mi++)
#pragma unroll
                for (int ni = 0; ni < 4; ni++) mma16816(acc[mi][ni], ah[mi], bl[ni]);

            uint32_t al[2][4];
#pragma unroll
            for (int mi = 0; mi < 2; mi++)
                ldsm_x4(al[mi], sb + SM_XL + (uint32_t)((aRow + mi * 16) * LDH + k0 + aKof) * 2);
#pragma unroll
            for (int mi = 0; mi < 2; mi++)
#pragma unroll
                for (int ni = 0; ni < 4; ni++) mma16816(acc[mi][ni], al[mi], bh[ni]);
        }

        // ---- interleaved COALESCED enc zero-fill (after k-loop) --------------------
        // Chunks 0-3: 10 rows, 4-6: 8 rows, 7: none (64 rows total).
        {
            int nrows = (chunk < 4) ? 10 : ((chunk < 7) ? 8 : 0);
            int rbase = (chunk < 4) ? chunk * 10 : 40 + (chunk - 4) * 8;
            const float4 z4 = make_float4(0.0f, 0.0f, 0.0f, 0.0f);
            for (int r = 0; r < nrows; r++) {
                float* row = encbase + (size_t)(rbase + r) * N_E;
                if (tid < 255) {
                    __stcs((float4*)(row + 2 + 4 * tid), z4);
                } else {
                    __stcs((float2*)row, make_float2(0.0f, 0.0f));
                    __stcs((float2*)(row + 1022), make_float2(0.0f, 0.0f));
                }
            }
        }

        // epilogue: quad-reduce into per-warp running best (no smem, no sync)
        float enr[8];
#pragma unroll
        for (int ni = 0; ni < 4; ni++) {
            int j = j0 + wn * 32 + ni * 8 + (lane & 3) * 2;
            enr[ni * 2]     = __ldg(&g_enorm_half[j]);
            enr[ni * 2 + 1] = __ldg(&g_enorm_half[j + 1]);
        }
#pragma unroll
        for (int mi = 0; mi < 2; mi++) {
#pragma unroll
            for (int h = 0; h < 2; h++) {
                float v = 3.4e38f; int ix = 0;
#pragma unroll
                for (int ni = 0; ni < 4; ni++) {
#pragma unroll
                    for (int bb = 0; bb < 2; bb++) {
                        float cand = enr[ni * 2 + bb] - acc[mi][ni][h * 2 + bb];
                        int col = j0 + wn * 32 + ni * 8 + (lane & 3) * 2 + bb;
                        if (cand < v) { v = cand; ix = col; }
                    }
                }
#pragma unroll
                for (int m = 1; m < 4; m <<= 1) {
                    float ov = __shfl_xor_sync(0xffffffffu, v, m);
                    int   oi = __shfl_xor_sync(0xffffffffu, ix, m);
                    if (ov < v || (ov == v && oi < ix)) { v = ov; ix = oi; }
                }
                int slot = mi * 2 + h;
                if (v < bestV[slot]) { bestV[slot] = v; bestI[slot] = ix; }
            }
        }
    }

    // ---- single cross-slab reduction at the end ---------------------------------------
    __syncthreads();   // all epilogues done; smem reuse safe
    if ((lane & 3) == 0) {
        int g = lane >> 2;
#pragma unroll
        for (int mi = 0; mi < 2; mi++) {
#pragma unroll
            for (int h = 0; h < 2; h++) {
                int row = wm * 32 + mi * 16 + g + h * 8;
                int slot = mi * 2 + h;
                redv[row * 4 + wn] = bestV[slot];
                redi[row * 4 + wn] = bestI[slot];
            }
        }
    }
    __syncthreads();
    if (tid < MQ) {
        float v = redv[tid * 4];
        int   ix = redi[tid * 4];
#pragma unroll
        for (int w = 1; w < 4; w++) {
            float ov = redv[tid * 4 + w];
            int   oi = redi[tid * 4 + w];
            if (ov < v || (ov == v && oi < ix)) { v = ov; ix = oi; }
        }
        sm_ix[tid] = ix;
        atomicAdd(&g_counts[ix], 1);
    }
    __syncthreads();   // orders all zero stores + sm_ix before hot stores

    // ---- hot one-hot stores: 64 scalar writes ---------------------------------------
    if (tid < MQ) {
        int idx = sm_ix[tid];
        __stcs(encbase + (size_t)tid * N_E + idx, 1.0f);
    }

    // ---- fused quantize + straight-through + loss -----------------------------------
    // Phase 1: gather ew rows into qt[k][h] across the dead EH+EL region; XH/XL survive.
    float* qt = (float*)(smem + SM_EH);   // [64][LDQ] = 16640 B (fits in 32768)
    {
        int h = tid & 63, quarter = tid >> 6;   // 4 threads per row, 16 dims each
        int idx = sm_ix[h];
        const float4* er = (const float4*)(ew + (size_t)idx * DIM + quarter * 16);
#pragma unroll
        for (int i = 0; i < 4; i++) {
            float4 v = er[i];
            int k = quarter * 16 + i * 4;
            qt[(k + 0) * LDQ + h] = v.x;
            qt[(k + 1) * LDQ + h] = v.y;
            qt[(k + 2) * LDQ + h] = v.z;
            qt[(k + 3) * LDQ + h] = v.w;
        }
    }
    __syncthreads();

    // Phase 2: x reconstructed from smem (hi+lo); no DRAM x re-read.
    float* qout = out + O_QUANT + (size_t)b * (DIM * HW) + hw0;
    float lsum = 0.0f;
#pragma unroll 4
    for (int i = 0; i < 16; i++) {
        int linear = i * 256 + tid;
        int k = linear >> 6, h = linear & 63;
        float xv = __half2float(Xs[h * LDH + k]) + __half2float(XLs[h * LDH + k]);
        float q  = qt[k * LDQ + h];
        float d  = q - xv;
        qout[(size_t)k * HW + h] = xv + d;   // straight-through forward value
        lsum += d * d;
    }
#pragma unroll
    for (int m = 16; m > 0; m >>= 1) lsum += __shfl_xor_sync(0xffffffffu, lsum, m);
    if (lane == 0) redv[wid] = lsum;
    __syncthreads();
    if (tid == 0) {
        float v = 0.0f;
#pragma unroll
        for (int w = 0; w < 8; w++) v += redv[w];
        atomicAdd(&g_loss_accum, v);
        __threadfence();
        unsigned prev = atomicAdd(&g_done, 1u);
        s_last = (prev == (unsigned)(gridDim.x - 1)) ? 1u : 0u;
    }
    __syncthreads();

    // ---- last CTA finalizes loss + perplexity ----------------------------------------
    if (s_last) {
        float s = 0.0f;
#pragma unroll
        for (int i = 0; i < 4; i++) {
            float p = (float)g_counts[tid * 4 + i] * (1.0f / 65536.0f);
            s += p * logf(p + 1e-10f);
        }
#pragma unroll
        for (int m = 16; m > 0; m >>= 1) s += __shfl_xor_sync(0xffffffffu, s, m);
        if (lane == 0) redv[wid] = s;
        __syncthreads();
        if (tid == 0) {
            float v = 0.0f;
#pragma unroll
            for (int w = 0; w < 8; w++) v += redv[w];
            out[O_PERP] = expf(-v);
            out[0] = 1.25f * g_loss_accum * (1.0f / (float)TOTAL);
        }
    }
}

// ---------------- launch ---------------------------------------------------------------
extern "C" void kernel_launch(void* const* d_in, const int* in_sizes, int n_in,
                              void* d_out, int out_size) {
    const float* x  = (const float*)d_in[0];
    const float* ew = (const float*)d_in[1];
    if (n_in >= 2 && in_sizes[0] == N_E * DIM && in_sizes[1] == TOTAL) {
        x  = (const float*)d_in[1];
        ew = (const float*)d_in[0];
    }
    float* out = (float*)d_out;

    prep_e_kernel<<<N_E / 8, 256>>>(ew);

    cudaFuncSetAttribute(argmin_mma_kernel,
                         cudaFuncAttributeMaxDynamicSharedMemorySize, SM_SZ);
    argmin_mma_kernel<<<N_Q / MQ, 256, SM_SZ>>>(x, ew, out);
}